// round 3
// baseline (speedup 1.0000x reference)
#include <cuda_runtime.h>
#include <cuda_bf16.h>
#include <stdint.h>

// Problem constants (fixed by the dataset)
#define NMAX   100000
#define EMAX   1600000
#define D      128
#define SCANB  1024

// ---------------- device scratch (allocation-free rule: __device__ globals) ----
__device__ float g_z[NMAX * D];
__device__ float g_y[NMAX * D];
__device__ float g_h1[NMAX * D];
__device__ float g_h2[NMAX * D];
__device__ int   g_col[EMAX];
__device__ int   g_rowptr[NMAX + 1];
__device__ int   g_cursor[NMAX];
__device__ int   g_deg[NMAX];
__device__ float g_invdeg[NMAX];
__device__ int   g_bsums[1024];

// ---------------- CSR build ---------------------------------------------------
__global__ void zero_deg_kernel(int* deg, int n) {
    int i = blockIdx.x * blockDim.x + threadIdx.x;
    if (i < n) deg[i] = 0;
}

__global__ void hist_kernel(const int* __restrict__ dst, int* __restrict__ deg, int e) {
    int i = blockIdx.x * blockDim.x + threadIdx.x;
    if (i < e) atomicAdd(&deg[dst[i]], 1);
}

__global__ void invdeg_kernel(const int* __restrict__ deg, float* __restrict__ invdeg, int n) {
    int i = blockIdx.x * blockDim.x + threadIdx.x;
    if (i < n) {
        int d = deg[i];
        invdeg[i] = 1.0f / (float)(d > 0 ? d : 1);
    }
}

__global__ void scanA_kernel(const int* __restrict__ deg, int* __restrict__ excl,
                             int* __restrict__ bsums, int n) {
    __shared__ int sh[SCANB];
    int tid = threadIdx.x;
    int i = blockIdx.x * SCANB + tid;
    int v = (i < n) ? deg[i] : 0;
    sh[tid] = v;
    __syncthreads();
    for (int off = 1; off < SCANB; off <<= 1) {
        int t = (tid >= off) ? sh[tid - off] : 0;
        __syncthreads();
        sh[tid] += t;
        __syncthreads();
    }
    if (i < n) excl[i] = sh[tid] - v;      // exclusive within block
    if (tid == SCANB - 1) bsums[blockIdx.x] = sh[tid];
}

__global__ void scanB_kernel(int* __restrict__ bsums, int nb) {
    __shared__ int sh[1024];
    int tid = threadIdx.x;
    int v = (tid < nb) ? bsums[tid] : 0;
    sh[tid] = v;
    __syncthreads();
    for (int off = 1; off < 1024; off <<= 1) {
        int t = (tid >= off) ? sh[tid - off] : 0;
        __syncthreads();
        sh[tid] += t;
        __syncthreads();
    }
    if (tid < nb) bsums[tid] = sh[tid] - v;  // exclusive block offsets
}

__global__ void scanC_kernel(int* __restrict__ rowptr, int* __restrict__ cursor,
                             const int* __restrict__ bsums, int n, int e) {
    int i = blockIdx.x * blockDim.x + threadIdx.x;
    if (i < n) {
        int r = rowptr[i] + bsums[i >> 10];
        rowptr[i] = r;
        cursor[i] = r;
    }
    if (i == 0) rowptr[n] = e;
}

__global__ void scatter_kernel(const int* __restrict__ src,
                               const int* __restrict__ dst,
                               int* __restrict__ cursor, int* __restrict__ col, int e) {
    int i = blockIdx.x * blockDim.x + threadIdx.x;
    if (i < e) {
        int d = dst[i];
        int s = src[i];
        int pos = atomicAdd(&cursor[d], 1);
        col[pos] = s;
    }
}

// ---------------- transform: z = h @ Wl^T ; y = h @ Wr^T + b -------------------
// Block tile: 64 rows x 256 cols (cols 0..127 -> z, 128..255 -> y).
// 256 threads, thread micro-tile 8 rows x 4 col-pairs, packed f32x2 FMA.
#define BM 64
#define KC 32

// packed dual-fp32 FMA: acc = a*b + acc (per 32-bit lane)
#define FMA_F32X2(acc, a, b) \
    asm("fma.rn.f32x2 %0, %1, %2, %0;" : "+l"(acc) : "l"(a), "l"(b))

__device__ __forceinline__ unsigned long long dup_f32(float v) {
    unsigned int u = __float_as_uint(v);
    return ((unsigned long long)u << 32) | (unsigned long long)u;
}
__device__ __forceinline__ float lo_f32(unsigned long long p) {
    return __uint_as_float((unsigned int)(p & 0xffffffffull));
}
__device__ __forceinline__ float hi_f32(unsigned long long p) {
    return __uint_as_float((unsigned int)(p >> 32));
}

__global__ __launch_bounds__(256) void transform_kernel(
    const float* __restrict__ h,
    const float* __restrict__ Wl, const float* __restrict__ Wr,
    const float* __restrict__ bias,
    float* __restrict__ z, float* __restrict__ yo, int n)
{
    __shared__ float ws[KC][256];                  // ws[k][j] = W_row_j[kb+k]  (32 KB)
    __shared__ unsigned long long hs2[BM][KC];     // duplicated (h,h) pairs     (16 KB)

    int tid = threadIdx.x;
    int tx = tid & 31;          // col group: cols tx*8 .. tx*8+7 (4 pairs)
    int ty = tid >> 5;          // row group: rows ty*8 .. ty*8+7
    int row0 = blockIdx.x * BM;
    int ty8 = ty * 8;
    int cb = tx * 8;

    unsigned long long acc2[8][4];
#pragma unroll
    for (int r = 0; r < 8; r++)
#pragma unroll
        for (int c = 0; c < 4; c++) acc2[r][c] = 0ull;

    for (int kb = 0; kb < D; kb += KC) {
        // load W chunk (transposed into ws)
        {
            int j = tid;  // 0..255
            const float* srcw = (j < 128) ? (Wl + j * D + kb) : (Wr + (j - 128) * D + kb);
#pragma unroll
            for (int q = 0; q < 8; q++) {
                float4 v = *(const float4*)(srcw + q * 4);
                ws[q * 4 + 0][j] = v.x;
                ws[q * 4 + 1][j] = v.y;
                ws[q * 4 + 2][j] = v.z;
                ws[q * 4 + 3][j] = v.w;
            }
        }
        // load h chunk: 64 rows x 32 floats, stored duplicated as f32x2
#pragma unroll
        for (int p = 0; p < 2; p++) {
            int id = tid + p * 256;
            int r = id >> 3;
            int slot = id & 7;
            int grow = row0 + r;
            float4 v = make_float4(0.f, 0.f, 0.f, 0.f);
            if (grow < n) v = *(const float4*)(h + (size_t)grow * D + kb + slot * 4);
            hs2[r][slot * 4 + 0] = dup_f32(v.x);
            hs2[r][slot * 4 + 1] = dup_f32(v.y);
            hs2[r][slot * 4 + 2] = dup_f32(v.z);
            hs2[r][slot * 4 + 3] = dup_f32(v.w);
        }
        __syncthreads();

#pragma unroll
        for (int k = 0; k < KC; k++) {
            const ulonglong2* wp = (const ulonglong2*)(&ws[k][cb]);
            ulonglong2 wA = wp[0];   // cols cb..cb+3 as 2 pairs
            ulonglong2 wB = wp[1];   // cols cb+4..cb+7
#pragma unroll
            for (int r = 0; r < 8; r++) {
                unsigned long long h2 = hs2[ty8 + r][k];   // uniform -> broadcast
                FMA_F32X2(acc2[r][0], h2, wA.x);
                FMA_F32X2(acc2[r][1], h2, wA.y);
                FMA_F32X2(acc2[r][2], h2, wB.x);
                FMA_F32X2(acc2[r][3], h2, wB.y);
            }
        }
        __syncthreads();
    }

    // epilogue
    if (cb < 128) {
#pragma unroll
        for (int r = 0; r < 8; r++) {
            int grow = row0 + ty8 + r;
            if (grow < n) {
                float4 a0 = make_float4(lo_f32(acc2[r][0]), hi_f32(acc2[r][0]),
                                        lo_f32(acc2[r][1]), hi_f32(acc2[r][1]));
                float4 a1 = make_float4(lo_f32(acc2[r][2]), hi_f32(acc2[r][2]),
                                        lo_f32(acc2[r][3]), hi_f32(acc2[r][3]));
                *(float4*)(z + (size_t)grow * D + cb) = a0;
                *(float4*)(z + (size_t)grow * D + cb + 4) = a1;
            }
        }
    } else {
        int c0 = cb - 128;
        float bv[8];
#pragma unroll
        for (int c = 0; c < 8; c++) bv[c] = bias[c0 + c];
#pragma unroll
        for (int r = 0; r < 8; r++) {
            int grow = row0 + ty8 + r;
            if (grow < n) {
                float4 a0 = make_float4(lo_f32(acc2[r][0]) + bv[0], hi_f32(acc2[r][0]) + bv[1],
                                        lo_f32(acc2[r][1]) + bv[2], hi_f32(acc2[r][1]) + bv[3]);
                float4 a1 = make_float4(lo_f32(acc2[r][2]) + bv[4], hi_f32(acc2[r][2]) + bv[5],
                                        lo_f32(acc2[r][3]) + bv[6], hi_f32(acc2[r][3]) + bv[7]);
                *(float4*)(yo + (size_t)grow * D + c0) = a0;
                *(float4*)(yo + (size_t)grow * D + c0 + 4) = a1;
            }
        }
    }
}

// ---------------- aggregation: out[i] = act(sum z[col] * invdeg + y) -----------
// One warp per node; each lane owns 4 contiguous floats (float4) of the row.
__global__ __launch_bounds__(256) void aggregate_kernel(
    const float* __restrict__ z, const float* __restrict__ y,
    const int* __restrict__ rowptr, const int* __restrict__ col,
    const float* __restrict__ invdeg, float* __restrict__ out,
    int n, int do_relu)
{
    int warp = (int)((blockIdx.x * blockDim.x + threadIdx.x) >> 5);
    int lane = threadIdx.x & 31;
    if (warp >= n) return;

    int beg = rowptr[warp];
    int end = rowptr[warp + 1];

    float4 acc = make_float4(0.f, 0.f, 0.f, 0.f);
    for (int e = beg; e < end; e++) {
        int s = __ldg(&col[e]);
        float4 v = *(const float4*)(z + (size_t)s * D + lane * 4);
        acc.x += v.x; acc.y += v.y; acc.z += v.z; acc.w += v.w;
    }
    float inv = invdeg[warp];
    float4 yv = *(const float4*)(y + (size_t)warp * D + lane * 4);
    float4 o;
    o.x = fmaf(acc.x, inv, yv.x);
    o.y = fmaf(acc.y, inv, yv.y);
    o.z = fmaf(acc.z, inv, yv.z);
    o.w = fmaf(acc.w, inv, yv.w);
    if (do_relu) {
        o.x = fmaxf(o.x, 0.f); o.y = fmaxf(o.y, 0.f);
        o.z = fmaxf(o.z, 0.f); o.w = fmaxf(o.w, 0.f);
    }
    *(float4*)(out + (size_t)warp * D + lane * 4) = o;
}

// ---------------- launch -------------------------------------------------------
extern "C" void kernel_launch(void* const* d_in, const int* in_sizes, int n_in,
                              void* d_out, int out_size) {
    const float* x  = (const float*)d_in[0];
    const int*   ei = (const int*)d_in[1];      // int32 (JAX downcasts int64 w/o x64)
    const float* Wl[3] = {(const float*)d_in[2], (const float*)d_in[5], (const float*)d_in[8]};
    const float* Wr[3] = {(const float*)d_in[3], (const float*)d_in[6], (const float*)d_in[9]};
    const float* bb[3] = {(const float*)d_in[4], (const float*)d_in[7], (const float*)d_in[10]};
    float* out = (float*)d_out;

    int n = in_sizes[0] / D;        // 100000
    int e = in_sizes[1] / 2;        // 1600000
    const int* src = ei;
    const int* dst = ei + e;

    // scratch pointers via symbol lookup (no allocation)
    float *p_z, *p_y, *p_h1, *p_h2, *p_invdeg;
    int *p_col, *p_rowptr, *p_cursor, *p_deg, *p_bsums;
    cudaGetSymbolAddress((void**)&p_z,      g_z);
    cudaGetSymbolAddress((void**)&p_y,      g_y);
    cudaGetSymbolAddress((void**)&p_h1,     g_h1);
    cudaGetSymbolAddress((void**)&p_h2,     g_h2);
    cudaGetSymbolAddress((void**)&p_invdeg, g_invdeg);
    cudaGetSymbolAddress((void**)&p_col,    g_col);
    cudaGetSymbolAddress((void**)&p_rowptr, g_rowptr);
    cudaGetSymbolAddress((void**)&p_cursor, g_cursor);
    cudaGetSymbolAddress((void**)&p_deg,    g_deg);
    cudaGetSymbolAddress((void**)&p_bsums,  g_bsums);

    int nb_n = (n + 255) / 256;
    int nb_e = (e + 255) / 256;
    int nb_scan = (n + SCANB - 1) / SCANB;

    // ---- CSR build (once per launch) ----
    zero_deg_kernel<<<nb_n, 256>>>(p_deg, n);
    hist_kernel<<<nb_e, 256>>>(dst, p_deg, e);
    invdeg_kernel<<<nb_n, 256>>>(p_deg, p_invdeg, n);
    scanA_kernel<<<nb_scan, SCANB>>>(p_deg, p_rowptr, p_bsums, n);
    scanB_kernel<<<1, 1024>>>(p_bsums, nb_scan);
    scanC_kernel<<<nb_n, 256>>>(p_rowptr, p_cursor, p_bsums, n, e);
    scatter_kernel<<<nb_e, 256>>>(src, dst, p_cursor, p_col, e);

    // ---- 3 layers: transform then aggregate ----
    int nb_tr = (n + BM - 1) / BM;                 // 1563
    int nb_ag = (n * 32 + 255) / 256;              // warp per node

    const float* hin = x;
    float* houts[3] = {p_h1, p_h2, out};
    for (int l = 0; l < 3; l++) {
        transform_kernel<<<nb_tr, 256>>>(hin, Wl[l], Wr[l], bb[l], p_z, p_y, n);
        aggregate_kernel<<<nb_ag, 256>>>(p_z, p_y, p_rowptr, p_col, p_invdeg,
                                         houts[l], n, (l < 2) ? 1 : 0);
        hin = houts[l];
    }
}

// round 5
// speedup vs baseline: 1.3804x; 1.3804x over previous
#include <cuda_runtime.h>
#include <cuda_bf16.h>
#include <stdint.h>

// Problem constants (fixed by the dataset)
#define NMAX   100000
#define EMAX   1600000
#define D      128
#define SCANB  1024

// ---------------- device scratch (allocation-free rule: __device__ globals) ----
__device__ float g_z[NMAX * D];
__device__ float g_y[NMAX * D];
__device__ float g_h1[NMAX * D];
__device__ float g_h2[NMAX * D];
__device__ int   g_col[EMAX];
__device__ int   g_rowptr[NMAX + 1];
__device__ int   g_cursor[NMAX];
__device__ int   g_deg[NMAX];
__device__ float g_invdeg[NMAX];
__device__ int   g_bsums[1024];

// ---------------- CSR build ---------------------------------------------------
__global__ void zero_deg_kernel(int* deg, int n) {
    int i = blockIdx.x * blockDim.x + threadIdx.x;
    if (i < n) deg[i] = 0;
}

__global__ void hist_kernel(const int* __restrict__ dst, int* __restrict__ deg, int e) {
    int i = blockIdx.x * blockDim.x + threadIdx.x;
    if (i < e) atomicAdd(&deg[dst[i]], 1);
}

__global__ void invdeg_kernel(const int* __restrict__ deg, float* __restrict__ invdeg, int n) {
    int i = blockIdx.x * blockDim.x + threadIdx.x;
    if (i < n) {
        int d = deg[i];
        invdeg[i] = 1.0f / (float)(d > 0 ? d : 1);
    }
}

__global__ void scanA_kernel(const int* __restrict__ deg, int* __restrict__ excl,
                             int* __restrict__ bsums, int n) {
    __shared__ int sh[SCANB];
    int tid = threadIdx.x;
    int i = blockIdx.x * SCANB + tid;
    int v = (i < n) ? deg[i] : 0;
    sh[tid] = v;
    __syncthreads();
    for (int off = 1; off < SCANB; off <<= 1) {
        int t = (tid >= off) ? sh[tid - off] : 0;
        __syncthreads();
        sh[tid] += t;
        __syncthreads();
    }
    if (i < n) excl[i] = sh[tid] - v;
    if (tid == SCANB - 1) bsums[blockIdx.x] = sh[tid];
}

__global__ void scanB_kernel(int* __restrict__ bsums, int nb) {
    __shared__ int sh[1024];
    int tid = threadIdx.x;
    int v = (tid < nb) ? bsums[tid] : 0;
    sh[tid] = v;
    __syncthreads();
    for (int off = 1; off < 1024; off <<= 1) {
        int t = (tid >= off) ? sh[tid - off] : 0;
        __syncthreads();
        sh[tid] += t;
        __syncthreads();
    }
    if (tid < nb) bsums[tid] = sh[tid] - v;
}

__global__ void scanC_kernel(int* __restrict__ rowptr, int* __restrict__ cursor,
                             const int* __restrict__ bsums, int n, int e) {
    int i = blockIdx.x * blockDim.x + threadIdx.x;
    if (i < n) {
        int r = rowptr[i] + bsums[i >> 10];
        rowptr[i] = r;
        cursor[i] = r;
    }
    if (i == 0) rowptr[n] = e;
}

__global__ void scatter_kernel(const int* __restrict__ src,
                               const int* __restrict__ dst,
                               int* __restrict__ cursor, int* __restrict__ col, int e) {
    int i = blockIdx.x * blockDim.x + threadIdx.x;
    if (i < e) {
        int d = dst[i];
        int s = src[i];
        int pos = atomicAdd(&cursor[d], 1);
        col[pos] = s;
    }
}

// ---------------- tensor-core transform (mma.sync, sm_80 PTX) ------------------
// Per CTA: 128 node rows x 256 out cols (0..127 -> z = h@Wl^T, 128..255 -> y = h@Wr^T + b).
// Split-bf16: h = hi + lo, W = Whi + Wlo; compute hi@Whi + lo@Whi + hi@Wlo, fp32 accum.
// SMEM A tile: 128 rows x 256 bf16 (k 0..127 = hi, 128..255 = lo), 512 B/row, XOR swizzle.
// SMEM B tile: 256 rows (n) x 256 bf16 ([Whi|Wlo]), same layout.
#define TF_A_OFF   0
#define TF_B_OFF   65536
#define TF_SMEM_SZ 196608

// swizzled byte offset within a tile for (row, bf16 col k); rows are 512 B.
__device__ __forceinline__ uint32_t sw_off(int row, int k) {
    int chunk = k >> 3;                       // 16B chunk index 0..31
    int swc = chunk ^ (row & 7);
    return (uint32_t)(row * 512 + swc * 16 + (k & 7) * 2);
}

__device__ __forceinline__ unsigned long long pack2x2(__nv_bfloat162 p0, __nv_bfloat162 p1) {
    unsigned int u0 = *(unsigned int*)&p0;
    unsigned int u1 = *(unsigned int*)&p1;
    return (unsigned long long)u0 | ((unsigned long long)u1 << 32);
}

// split a float4 into hi/lo bf16 packed 8-byte values
__device__ __forceinline__ void split_f4(float4 v, unsigned long long& hi8,
                                         unsigned long long& lo8) {
    __nv_bfloat162 h01 = __floats2bfloat162_rn(v.x, v.y);
    __nv_bfloat162 h23 = __floats2bfloat162_rn(v.z, v.w);
    float r0 = v.x - __low2float(h01);
    float r1 = v.y - __high2float(h01);
    float r2 = v.z - __low2float(h23);
    float r3 = v.w - __high2float(h23);
    __nv_bfloat162 l01 = __floats2bfloat162_rn(r0, r1);
    __nv_bfloat162 l23 = __floats2bfloat162_rn(r2, r3);
    hi8 = pack2x2(h01, h23);
    lo8 = pack2x2(l01, l23);
}

__device__ __forceinline__ uint32_t smem_u32(const void* p) {
    uint32_t a;
    asm("{ .reg .u64 t; cvta.to.shared.u64 t, %1; cvt.u32.u64 %0, t; }" : "=r"(a) : "l"(p));
    return a;
}

#define LDSM_X4(d0, d1, d2, d3, addr) \
    asm volatile("ldmatrix.sync.aligned.m8n8.x4.shared.b16 {%0,%1,%2,%3}, [%4];" \
                 : "=r"(d0), "=r"(d1), "=r"(d2), "=r"(d3) : "r"(addr))

#define MMA_BF16(d, a, b) \
    asm volatile("mma.sync.aligned.m16n8k16.row.col.f32.bf16.bf16.f32 " \
                 "{%0,%1,%2,%3}, {%4,%5,%6,%7}, {%8,%9}, {%0,%1,%2,%3};" \
                 : "+f"((d)[0]), "+f"((d)[1]), "+f"((d)[2]), "+f"((d)[3]) \
                 : "r"((a)[0]), "r"((a)[1]), "r"((a)[2]), "r"((a)[3]), \
                   "r"((b)[0]), "r"((b)[1]))

__global__ __launch_bounds__(512) void transform_mma_kernel(
    const float* __restrict__ h,
    const float* __restrict__ Wl, const float* __restrict__ Wr,
    const float* __restrict__ bias,
    float* __restrict__ z, float* __restrict__ yo, int n)
{
    extern __shared__ char smem[];
    const uint32_t sa = smem_u32(smem) + TF_A_OFF;
    const uint32_t sb = smem_u32(smem) + TF_B_OFF;
    int tid = threadIdx.x;
    int row0 = blockIdx.x * 128;

    // ---- convert A: 128 rows x 128 fp32 -> hi|lo bf16 swizzled (4096 float4) ----
#pragma unroll
    for (int it = 0; it < 8; it++) {
        int idx = tid + it * 512;
        int r = idx >> 5;
        int q = idx & 31;          // float4 slot, k = q*4
        int grow = row0 + r;
        float4 v = make_float4(0.f, 0.f, 0.f, 0.f);
        if (grow < n) v = *(const float4*)(h + (size_t)grow * D + q * 4);
        unsigned long long hi8, lo8;
        split_f4(v, hi8, lo8);
        *(unsigned long long*)(smem + TF_A_OFF + sw_off(r, q * 4))       = hi8;
        *(unsigned long long*)(smem + TF_A_OFF + sw_off(r, 128 + q * 4)) = lo8;
    }
    // ---- convert B: rows 0..127 = Wl, 128..255 = Wr (8192 float4) ----
#pragma unroll
    for (int it = 0; it < 16; it++) {
        int idx = tid + it * 512;
        int j = idx >> 5;
        int q = idx & 31;
        const float* srcw = (j < 128) ? (Wl + (size_t)j * D + q * 4)
                                      : (Wr + (size_t)(j - 128) * D + q * 4);
        float4 v = *(const float4*)srcw;
        unsigned long long hi8, lo8;
        split_f4(v, hi8, lo8);
        *(unsigned long long*)(smem + TF_B_OFF + sw_off(j, q * 4))       = hi8;
        *(unsigned long long*)(smem + TF_B_OFF + sw_off(j, 128 + q * 4)) = lo8;
    }
    __syncthreads();

    // ---- warp tiling: 16 warps, each 32 rows x 64 cols ----
    int wid = tid >> 5;
    int lane = tid & 31;
    int wm = wid >> 2;           // 0..3 -> row block of 32
    int wn = wid & 3;            // 0..3 -> col block of 64
    int R = wm * 32;
    int C = wn * 64;

    float acc[2][8][4];
#pragma unroll
    for (int mt = 0; mt < 2; mt++)
#pragma unroll
        for (int nt = 0; nt < 8; nt++)
#pragma unroll
            for (int i = 0; i < 4; i++) acc[mt][nt][i] = 0.f;

    // ldmatrix lane address components
    int a_r = (lane & 7) + ((lane >> 3) & 1) * 8;   // row within 16
    int a_k = ((lane >> 4) & 1) * 8;                // k offset within 16
    int b_n = (lane & 7) + ((lane >> 4) & 1) * 8;   // n within 16 (2 ntiles)
    int b_k = ((lane >> 3) & 1) * 8;

#pragma unroll
    for (int term = 0; term < 3; term++) {
        int kab = (term == 1) ? 128 : 0;   // A uses lo for term 1
        int kbb = (term == 2) ? 128 : 0;   // B uses lo for term 2
#pragma unroll
        for (int kc = 0; kc < 8; kc++) {
            int ka = kab + kc * 16 + a_k;
            int kb = kbb + kc * 16 + b_k;
            uint32_t afr[2][4];
#pragma unroll
            for (int mt = 0; mt < 2; mt++) {
                uint32_t addr = sa + sw_off(R + mt * 16 + a_r, ka);
                LDSM_X4(afr[mt][0], afr[mt][1], afr[mt][2], afr[mt][3], addr);
            }
            uint32_t bfr[8][2];
#pragma unroll
            for (int p = 0; p < 4; p++) {
                uint32_t addr = sb + sw_off(C + p * 16 + b_n, kb);
                uint32_t d0, d1, d2, d3;
                LDSM_X4(d0, d1, d2, d3, addr);
                bfr[p * 2][0] = d0;     bfr[p * 2][1] = d1;
                bfr[p * 2 + 1][0] = d2; bfr[p * 2 + 1][1] = d3;
            }
#pragma unroll
            for (int mt = 0; mt < 2; mt++)
#pragma unroll
                for (int nt = 0; nt < 8; nt++)
                    MMA_BF16(acc[mt][nt], afr[mt], bfr[nt]);
        }
    }

    // ---- epilogue ----
    int g = lane >> 2;
    int tg = lane & 3;
#pragma unroll
    for (int mt = 0; mt < 2; mt++) {
        int r0g = row0 + R + mt * 16 + g;
        int r1g = r0g + 8;
        bool ok0 = (r0g < n), ok1 = (r1g < n);
#pragma unroll
        for (int nt = 0; nt < 8; nt++) {
            int colg = C + nt * 8 + tg * 2;
            if (colg < 128) {
                if (ok0) *(float2*)(z + (size_t)r0g * D + colg) =
                    make_float2(acc[mt][nt][0], acc[mt][nt][1]);
                if (ok1) *(float2*)(z + (size_t)r1g * D + colg) =
                    make_float2(acc[mt][nt][2], acc[mt][nt][3]);
            } else {
                int yc = colg - 128;
                float b0 = __ldg(&bias[yc]);
                float b1 = __ldg(&bias[yc + 1]);
                if (ok0) *(float2*)(yo + (size_t)r0g * D + yc) =
                    make_float2(acc[mt][nt][0] + b0, acc[mt][nt][1] + b1);
                if (ok1) *(float2*)(yo + (size_t)r1g * D + yc) =
                    make_float2(acc[mt][nt][2] + b0, acc[mt][nt][3] + b1);
            }
        }
    }
}

// ---------------- aggregation: out[i] = act(sum z[col] * invdeg + y) -----------
__global__ __launch_bounds__(256) void aggregate_kernel(
    const float* __restrict__ z, const float* __restrict__ y,
    const int* __restrict__ rowptr, const int* __restrict__ col,
    const float* __restrict__ invdeg, float* __restrict__ out,
    int n, int do_relu)
{
    int warp = (int)((blockIdx.x * blockDim.x + threadIdx.x) >> 5);
    int lane = threadIdx.x & 31;
    if (warp >= n) return;

    int beg = rowptr[warp];
    int end = rowptr[warp + 1];

    float4 acc = make_float4(0.f, 0.f, 0.f, 0.f);
    for (int e = beg; e < end; e++) {
        int s = __ldg(&col[e]);
        float4 v = *(const float4*)(z + (size_t)s * D + lane * 4);
        acc.x += v.x; acc.y += v.y; acc.z += v.z; acc.w += v.w;
    }
    float inv = invdeg[warp];
    float4 yv = *(const float4*)(y + (size_t)warp * D + lane * 4);
    float4 o;
    o.x = fmaf(acc.x, inv, yv.x);
    o.y = fmaf(acc.y, inv, yv.y);
    o.z = fmaf(acc.z, inv, yv.z);
    o.w = fmaf(acc.w, inv, yv.w);
    if (do_relu) {
        o.x = fmaxf(o.x, 0.f); o.y = fmaxf(o.y, 0.f);
        o.z = fmaxf(o.z, 0.f); o.w = fmaxf(o.w, 0.f);
    }
    *(float4*)(out + (size_t)warp * D + lane * 4) = o;
}

// ---------------- launch -------------------------------------------------------
extern "C" void kernel_launch(void* const* d_in, const int* in_sizes, int n_in,
                              void* d_out, int out_size) {
    const float* x  = (const float*)d_in[0];
    const int*   ei = (const int*)d_in[1];      // int32 (JAX downcasts int64 w/o x64)
    const float* Wl[3] = {(const float*)d_in[2], (const float*)d_in[5], (const float*)d_in[8]};
    const float* Wr[3] = {(const float*)d_in[3], (const float*)d_in[6], (const float*)d_in[9]};
    const float* bb[3] = {(const float*)d_in[4], (const float*)d_in[7], (const float*)d_in[10]};
    float* out = (float*)d_out;

    int n = in_sizes[0] / D;        // 100000
    int e = in_sizes[1] / 2;        // 1600000
    const int* src = ei;
    const int* dst = ei + e;

    float *p_z, *p_y, *p_h1, *p_h2, *p_invdeg;
    int *p_col, *p_rowptr, *p_cursor, *p_deg, *p_bsums;
    cudaGetSymbolAddress((void**)&p_z,      g_z);
    cudaGetSymbolAddress((void**)&p_y,      g_y);
    cudaGetSymbolAddress((void**)&p_h1,     g_h1);
    cudaGetSymbolAddress((void**)&p_h2,     g_h2);
    cudaGetSymbolAddress((void**)&p_invdeg, g_invdeg);
    cudaGetSymbolAddress((void**)&p_col,    g_col);
    cudaGetSymbolAddress((void**)&p_rowptr, g_rowptr);
    cudaGetSymbolAddress((void**)&p_cursor, g_cursor);
    cudaGetSymbolAddress((void**)&p_deg,    g_deg);
    cudaGetSymbolAddress((void**)&p_bsums,  g_bsums);

    static int smem_set = 0;
    if (!smem_set) {
        cudaFuncSetAttribute(transform_mma_kernel,
                             cudaFuncAttributeMaxDynamicSharedMemorySize, TF_SMEM_SZ);
        smem_set = 1;
    }

    int nb_n = (n + 255) / 256;
    int nb_e = (e + 255) / 256;
    int nb_scan = (n + SCANB - 1) / SCANB;

    // ---- CSR build (once per launch) ----
    zero_deg_kernel<<<nb_n, 256>>>(p_deg, n);
    hist_kernel<<<nb_e, 256>>>(dst, p_deg, e);
    invdeg_kernel<<<nb_n, 256>>>(p_deg, p_invdeg, n);
    scanA_kernel<<<nb_scan, SCANB>>>(p_deg, p_rowptr, p_bsums, n);
    scanB_kernel<<<1, 1024>>>(p_bsums, nb_scan);
    scanC_kernel<<<nb_n, 256>>>(p_rowptr, p_cursor, p_bsums, n, e);
    scatter_kernel<<<nb_e, 256>>>(src, dst, p_cursor, p_col, e);

    // ---- 3 layers ----
    int nb_tf = (n + 127) / 128;                   // 782
    int nb_ag = (n * 32 + 255) / 256;

    const float* hin = x;
    float* houts[3] = {p_h1, p_h2, out};
    for (int l = 0; l < 3; l++) {
        transform_mma_kernel<<<nb_tf, 512, TF_SMEM_SZ>>>(hin, Wl[l], Wr[l], bb[l],
                                                         p_z, p_y, n);
        aggregate_kernel<<<nb_ag, 256>>>(p_z, p_y, p_rowptr, p_col, p_invdeg,
                                         houts[l], n, (l < 2) ? 1 : 0);
        hin = houts[l];
    }
}

// round 6
// speedup vs baseline: 1.4547x; 1.0539x over previous
#include <cuda_runtime.h>
#include <cuda_bf16.h>
#include <stdint.h>

// Problem constants (fixed by the dataset)
#define NMAX   100000
#define EMAX   1600000
#define D      128
#define SCANB  1024

// ---------------- device scratch (allocation-free rule: __device__ globals) ----
__device__ float g_z[NMAX * D];
__device__ float g_y[NMAX * D];
__device__ float g_h1[NMAX * D];
__device__ float g_h2[NMAX * D];
__device__ int   g_col[EMAX];
__device__ int   g_rowptr[NMAX + 1];
__device__ int   g_cursor[NMAX];
__device__ int   g_deg[NMAX];
__device__ float g_invdeg[NMAX];
__device__ int   g_bsums[1024];
// pre-converted, pre-swizzled W tile images (split-bf16), one per layer
__device__ __align__(16) char g_wimg[3][131072];

// ---------------- CSR build ---------------------------------------------------
__global__ void zero_deg_kernel(int* deg, int n) {
    int i = blockIdx.x * blockDim.x + threadIdx.x;
    if (i < n) deg[i] = 0;
}

__global__ void hist_kernel(const int* __restrict__ dst, int* __restrict__ deg, int e) {
    int i = blockIdx.x * blockDim.x + threadIdx.x;
    if (i < e) atomicAdd(&deg[dst[i]], 1);
}

__global__ void invdeg_kernel(const int* __restrict__ deg, float* __restrict__ invdeg, int n) {
    int i = blockIdx.x * blockDim.x + threadIdx.x;
    if (i < n) {
        int d = deg[i];
        invdeg[i] = 1.0f / (float)(d > 0 ? d : 1);
    }
}

__global__ void scanA_kernel(const int* __restrict__ deg, int* __restrict__ excl,
                             int* __restrict__ bsums, int n) {
    __shared__ int sh[SCANB];
    int tid = threadIdx.x;
    int i = blockIdx.x * SCANB + tid;
    int v = (i < n) ? deg[i] : 0;
    sh[tid] = v;
    __syncthreads();
    for (int off = 1; off < SCANB; off <<= 1) {
        int t = (tid >= off) ? sh[tid - off] : 0;
        __syncthreads();
        sh[tid] += t;
        __syncthreads();
    }
    if (i < n) excl[i] = sh[tid] - v;
    if (tid == SCANB - 1) bsums[blockIdx.x] = sh[tid];
}

__global__ void scanB_kernel(int* __restrict__ bsums, int nb) {
    __shared__ int sh[1024];
    int tid = threadIdx.x;
    int v = (tid < nb) ? bsums[tid] : 0;
    sh[tid] = v;
    __syncthreads();
    for (int off = 1; off < 1024; off <<= 1) {
        int t = (tid >= off) ? sh[tid - off] : 0;
        __syncthreads();
        sh[tid] += t;
        __syncthreads();
    }
    if (tid < nb) bsums[tid] = sh[tid] - v;
}

__global__ void scanC_kernel(int* __restrict__ rowptr, int* __restrict__ cursor,
                             const int* __restrict__ bsums, int n, int e) {
    int i = blockIdx.x * blockDim.x + threadIdx.x;
    if (i < n) {
        int r = rowptr[i] + bsums[i >> 10];
        rowptr[i] = r;
        cursor[i] = r;
    }
    if (i == 0) rowptr[n] = e;
}

__global__ void scatter_kernel(const int* __restrict__ src,
                               const int* __restrict__ dst,
                               int* __restrict__ cursor, int* __restrict__ col, int e) {
    int i = blockIdx.x * blockDim.x + threadIdx.x;
    if (i < e) {
        int d = dst[i];
        int s = src[i];
        int pos = atomicAdd(&cursor[d], 1);
        col[pos] = s;
    }
}

// ---------------- shared helpers -----------------------------------------------
// swizzled byte offset within a tile for (row, bf16 col k); rows are 512 B.
__device__ __forceinline__ uint32_t sw_off(int row, int k) {
    int chunk = k >> 3;                       // 16B chunk index 0..31
    int swc = chunk ^ (row & 7);
    return (uint32_t)(row * 512 + swc * 16 + (k & 7) * 2);
}

__device__ __forceinline__ unsigned long long pack2x2(__nv_bfloat162 p0, __nv_bfloat162 p1) {
    unsigned int u0 = *(unsigned int*)&p0;
    unsigned int u1 = *(unsigned int*)&p1;
    return (unsigned long long)u0 | ((unsigned long long)u1 << 32);
}

// split a float4 into hi/lo bf16 packed 8-byte values
__device__ __forceinline__ void split_f4(float4 v, unsigned long long& hi8,
                                         unsigned long long& lo8) {
    __nv_bfloat162 h01 = __floats2bfloat162_rn(v.x, v.y);
    __nv_bfloat162 h23 = __floats2bfloat162_rn(v.z, v.w);
    float r0 = v.x - __low2float(h01);
    float r1 = v.y - __high2float(h01);
    float r2 = v.z - __low2float(h23);
    float r3 = v.w - __high2float(h23);
    __nv_bfloat162 l01 = __floats2bfloat162_rn(r0, r1);
    __nv_bfloat162 l23 = __floats2bfloat162_rn(r2, r3);
    hi8 = pack2x2(h01, h23);
    lo8 = pack2x2(l01, l23);
}

__device__ __forceinline__ uint32_t smem_u32(const void* p) {
    uint32_t a;
    asm("{ .reg .u64 t; cvta.to.shared.u64 t, %1; cvt.u32.u64 %0, t; }" : "=r"(a) : "l"(p));
    return a;
}

#define LDSM_X4(d0, d1, d2, d3, addr) \
    asm volatile("ldmatrix.sync.aligned.m8n8.x4.shared.b16 {%0,%1,%2,%3}, [%4];" \
                 : "=r"(d0), "=r"(d1), "=r"(d2), "=r"(d3) : "r"(addr))

#define MMA_BF16(d, a, b) \
    asm volatile("mma.sync.aligned.m16n8k16.row.col.f32.bf16.bf16.f32 " \
                 "{%0,%1,%2,%3}, {%4,%5,%6,%7}, {%8,%9}, {%0,%1,%2,%3};" \
                 : "+f"((d)[0]), "+f"((d)[1]), "+f"((d)[2]), "+f"((d)[3]) \
                 : "r"((a)[0]), "r"((a)[1]), "r"((a)[2]), "r"((a)[3]), \
                   "r"((b)[0]), "r"((b)[1]))

// ---------------- W pre-convert: fp32 -> split-bf16, swizzled tile image -------
// image rows 0..127 = Wl, 128..255 = Wr; k 0..127 = hi, 128..255 = lo.
__global__ __launch_bounds__(256) void convert_w_kernel(
    const float* __restrict__ Wl, const float* __restrict__ Wr, char* __restrict__ img)
{
    int idx = blockIdx.x * blockDim.x + threadIdx.x;   // 0..8191
    if (idx >= 8192) return;
    int j = idx >> 5;
    int q = idx & 31;
    const float* srcw = (j < 128) ? (Wl + (size_t)j * D + q * 4)
                                  : (Wr + (size_t)(j - 128) * D + q * 4);
    float4 v = *(const float4*)srcw;
    unsigned long long hi8, lo8;
    split_f4(v, hi8, lo8);
    *(unsigned long long*)(img + sw_off(j, q * 4))       = hi8;
    *(unsigned long long*)(img + sw_off(j, 128 + q * 4)) = lo8;
}

// ---------------- tensor-core transform (persistent CTAs) ----------------------
// Per row-tile: 128 node rows x 256 out cols (0..127 -> z = h@Wl^T, 128..255 -> y).
// W tile loaded into SMEM ONCE per CTA (pre-converted image, straight copy),
// then CTA loops row-tiles with grid stride.
#define TF_A_OFF   0
#define TF_B_OFF   65536
#define TF_SMEM_SZ 196608

__global__ __launch_bounds__(512) void transform_mma_kernel(
    const float* __restrict__ h,
    const char* __restrict__ wimg,
    const float* __restrict__ bias,
    float* __restrict__ z, float* __restrict__ yo, int n, int ntiles)
{
    extern __shared__ char smem[];
    const uint32_t sa = smem_u32(smem) + TF_A_OFF;
    const uint32_t sb = smem_u32(smem) + TF_B_OFF;
    int tid = threadIdx.x;

    // ---- load pre-converted W tile (131072 B straight copy) ----
    {
        const float4* wsrc = (const float4*)wimg;
        float4* bdst = (float4*)(smem + TF_B_OFF);
#pragma unroll
        for (int it = 0; it < 16; it++)
            bdst[tid + it * 512] = wsrc[tid + it * 512];
    }

    int wid = tid >> 5;
    int lane = tid & 31;
    int wm = wid >> 2;           // 0..3 -> row block of 32
    int wn = wid & 3;            // 0..3 -> col block of 64
    int R = wm * 32;
    int C = wn * 64;

    // ldmatrix lane address components
    int a_r = (lane & 7) + ((lane >> 3) & 1) * 8;
    int a_k = ((lane >> 4) & 1) * 8;
    int b_n = (lane & 7) + ((lane >> 4) & 1) * 8;
    int b_k = ((lane >> 3) & 1) * 8;
    int g  = lane >> 2;
    int tg = lane & 3;

    for (int tile = blockIdx.x; tile < ntiles; tile += gridDim.x) {
        int row0 = tile * 128;

        // ---- convert A: 128 rows x 128 fp32 -> hi|lo bf16 swizzled ----
        __syncthreads();   // prior iteration's ldmatrix reads must be done
#pragma unroll
        for (int it = 0; it < 8; it++) {
            int idx = tid + it * 512;
            int r = idx >> 5;
            int q = idx & 31;
            int grow = row0 + r;
            float4 v = make_float4(0.f, 0.f, 0.f, 0.f);
            if (grow < n) v = *(const float4*)(h + (size_t)grow * D + q * 4);
            unsigned long long hi8, lo8;
            split_f4(v, hi8, lo8);
            *(unsigned long long*)(smem + TF_A_OFF + sw_off(r, q * 4))       = hi8;
            *(unsigned long long*)(smem + TF_A_OFF + sw_off(r, 128 + q * 4)) = lo8;
        }
        __syncthreads();

        float acc[2][8][4];
#pragma unroll
        for (int mt = 0; mt < 2; mt++)
#pragma unroll
            for (int nt = 0; nt < 8; nt++)
#pragma unroll
                for (int i = 0; i < 4; i++) acc[mt][nt][i] = 0.f;

#pragma unroll
        for (int term = 0; term < 3; term++) {
            int kab = (term == 1) ? 128 : 0;   // A uses lo for term 1
            int kbb = (term == 2) ? 128 : 0;   // B uses lo for term 2
#pragma unroll
            for (int kc = 0; kc < 8; kc++) {
                int ka = kab + kc * 16 + a_k;
                int kb = kbb + kc * 16 + b_k;
                uint32_t afr[2][4];
#pragma unroll
                for (int mt = 0; mt < 2; mt++) {
                    uint32_t addr = sa + sw_off(R + mt * 16 + a_r, ka);
                    LDSM_X4(afr[mt][0], afr[mt][1], afr[mt][2], afr[mt][3], addr);
                }
                uint32_t bfr[8][2];
#pragma unroll
                for (int p = 0; p < 4; p++) {
                    uint32_t addr = sb + sw_off(C + p * 16 + b_n, kb);
                    uint32_t d0, d1, d2, d3;
                    LDSM_X4(d0, d1, d2, d3, addr);
                    bfr[p * 2][0] = d0;     bfr[p * 2][1] = d1;
                    bfr[p * 2 + 1][0] = d2; bfr[p * 2 + 1][1] = d3;
                }
#pragma unroll
                for (int mt = 0; mt < 2; mt++)
#pragma unroll
                    for (int nt = 0; nt < 8; nt++)
                        MMA_BF16(acc[mt][nt], afr[mt], bfr[nt]);
            }
        }

        // ---- epilogue (registers -> global; no SMEM) ----
#pragma unroll
        for (int mt = 0; mt < 2; mt++) {
            int r0g = row0 + R + mt * 16 + g;
            int r1g = r0g + 8;
            bool ok0 = (r0g < n), ok1 = (r1g < n);
#pragma unroll
            for (int nt = 0; nt < 8; nt++) {
                int colg = C + nt * 8 + tg * 2;
                if (colg < 128) {
                    if (ok0) *(float2*)(z + (size_t)r0g * D + colg) =
                        make_float2(acc[mt][nt][0], acc[mt][nt][1]);
                    if (ok1) *(float2*)(z + (size_t)r1g * D + colg) =
                        make_float2(acc[mt][nt][2], acc[mt][nt][3]);
                } else {
                    int yc = colg - 128;
                    float b0 = __ldg(&bias[yc]);
                    float b1 = __ldg(&bias[yc + 1]);
                    if (ok0) *(float2*)(yo + (size_t)r0g * D + yc) =
                        make_float2(acc[mt][nt][0] + b0, acc[mt][nt][1] + b1);
                    if (ok1) *(float2*)(yo + (size_t)r1g * D + yc) =
                        make_float2(acc[mt][nt][2] + b0, acc[mt][nt][3] + b1);
                }
            }
        }
    }
}

// ---------------- aggregation: out[i] = act(sum z[col] * invdeg + y) -----------
__global__ __launch_bounds__(256) void aggregate_kernel(
    const float* __restrict__ z, const float* __restrict__ y,
    const int* __restrict__ rowptr, const int* __restrict__ col,
    const float* __restrict__ invdeg, float* __restrict__ out,
    int n, int do_relu)
{
    int warp = (int)((blockIdx.x * blockDim.x + threadIdx.x) >> 5);
    int lane = threadIdx.x & 31;
    if (warp >= n) return;

    int beg = rowptr[warp];
    int end = rowptr[warp + 1];

    float4 acc = make_float4(0.f, 0.f, 0.f, 0.f);
    for (int e = beg; e < end; e++) {
        int s = __ldg(&col[e]);
        float4 v = *(const float4*)(z + (size_t)s * D + lane * 4);
        acc.x += v.x; acc.y += v.y; acc.z += v.z; acc.w += v.w;
    }
    float inv = invdeg[warp];
    float4 yv = *(const float4*)(y + (size_t)warp * D + lane * 4);
    float4 o;
    o.x = fmaf(acc.x, inv, yv.x);
    o.y = fmaf(acc.y, inv, yv.y);
    o.z = fmaf(acc.z, inv, yv.z);
    o.w = fmaf(acc.w, inv, yv.w);
    if (do_relu) {
        o.x = fmaxf(o.x, 0.f); o.y = fmaxf(o.y, 0.f);
        o.z = fmaxf(o.z, 0.f); o.w = fmaxf(o.w, 0.f);
    }
    *(float4*)(out + (size_t)warp * D + lane * 4) = o;
}

// ---------------- launch -------------------------------------------------------
extern "C" void kernel_launch(void* const* d_in, const int* in_sizes, int n_in,
                              void* d_out, int out_size) {
    const float* x  = (const float*)d_in[0];
    const int*   ei = (const int*)d_in[1];      // int32 (JAX downcasts int64 w/o x64)
    const float* Wl[3] = {(const float*)d_in[2], (const float*)d_in[5], (const float*)d_in[8]};
    const float* Wr[3] = {(const float*)d_in[3], (const float*)d_in[6], (const float*)d_in[9]};
    const float* bb[3] = {(const float*)d_in[4], (const float*)d_in[7], (const float*)d_in[10]};
    float* out = (float*)d_out;

    int n = in_sizes[0] / D;        // 100000
    int e = in_sizes[1] / 2;        // 1600000
    const int* src = ei;
    const int* dst = ei + e;

    float *p_z, *p_y, *p_h1, *p_h2, *p_invdeg;
    int *p_col, *p_rowptr, *p_cursor, *p_deg, *p_bsums;
    char* p_wimg;
    cudaGetSymbolAddress((void**)&p_z,      g_z);
    cudaGetSymbolAddress((void**)&p_y,      g_y);
    cudaGetSymbolAddress((void**)&p_h1,     g_h1);
    cudaGetSymbolAddress((void**)&p_h2,     g_h2);
    cudaGetSymbolAddress((void**)&p_invdeg, g_invdeg);
    cudaGetSymbolAddress((void**)&p_col,    g_col);
    cudaGetSymbolAddress((void**)&p_rowptr, g_rowptr);
    cudaGetSymbolAddress((void**)&p_cursor, g_cursor);
    cudaGetSymbolAddress((void**)&p_deg,    g_deg);
    cudaGetSymbolAddress((void**)&p_bsums,  g_bsums);
    cudaGetSymbolAddress((void**)&p_wimg,   g_wimg);

    static int smem_set = 0;
    if (!smem_set) {
        cudaFuncSetAttribute(transform_mma_kernel,
                             cudaFuncAttributeMaxDynamicSharedMemorySize, TF_SMEM_SZ);
        smem_set = 1;
    }

    int nb_n = (n + 255) / 256;
    int nb_e = (e + 255) / 256;
    int nb_scan = (n + SCANB - 1) / SCANB;

    // ---- CSR build + W pre-convert (once per launch) ----
    zero_deg_kernel<<<nb_n, 256>>>(p_deg, n);
    hist_kernel<<<nb_e, 256>>>(dst, p_deg, e);
    invdeg_kernel<<<nb_n, 256>>>(p_deg, p_invdeg, n);
    scanA_kernel<<<nb_scan, SCANB>>>(p_deg, p_rowptr, p_bsums, n);
    scanB_kernel<<<1, 1024>>>(p_bsums, nb_scan);
    scanC_kernel<<<nb_n, 256>>>(p_rowptr, p_cursor, p_bsums, n, e);
    scatter_kernel<<<nb_e, 256>>>(src, dst, p_cursor, p_col, e);
    for (int l = 0; l < 3; l++)
        convert_w_kernel<<<32, 256>>>(Wl[l], Wr[l], p_wimg + (size_t)l * 131072);

    // ---- 3 layers ----
    int ntiles = (n + 127) / 128;                  // 782
    int nb_ag = (n * 32 + 255) / 256;

    const float* hin = x;
    float* houts[3] = {p_h1, p_h2, out};
    for (int l = 0; l < 3; l++) {
        transform_mma_kernel<<<148, 512, TF_SMEM_SZ>>>(hin, p_wimg + (size_t)l * 131072,
                                                       bb[l], p_z, p_y, n, ntiles);
        aggregate_kernel<<<nb_ag, 256>>>(p_z, p_y, p_rowptr, p_col, p_invdeg,
                                         houts[l], n, (l < 2) ? 1 : 0);
        hin = houts[l];
    }
}

// round 7
// speedup vs baseline: 2.0996x; 1.4433x over previous
#include <cuda_runtime.h>
#include <cuda_bf16.h>
#include <stdint.h>

// Problem constants (fixed by the dataset)
#define NMAX   100000
#define EMAX   1600000
#define D      128
#define SCANB  1024

// ---------------- device scratch (allocation-free rule: __device__ globals) ----
__device__ float g_z[NMAX * D];
__device__ float g_y[NMAX * D];
__device__ float g_h1[NMAX * D];
__device__ float g_h2[NMAX * D];
__device__ int   g_col[EMAX];
__device__ int   g_rowptr[NMAX + 1];
__device__ int   g_cursor[NMAX];
__device__ int   g_deg[NMAX];
__device__ float g_invdeg[NMAX];
__device__ int   g_bsums[1024];
// pre-converted, pre-swizzled W tile images (split-bf16), one per layer
__device__ __align__(16) char g_wimg[3][131072];

// ---------------- CSR build ---------------------------------------------------
__global__ void zero_deg_kernel(int* deg, int n) {
    int i = blockIdx.x * blockDim.x + threadIdx.x;
    if (i < n) deg[i] = 0;
}

__global__ void hist_kernel(const int* __restrict__ dst, int* __restrict__ deg, int e) {
    int i = blockIdx.x * blockDim.x + threadIdx.x;
    if (i < e) atomicAdd(&deg[dst[i]], 1);
}

__global__ void invdeg_kernel(const int* __restrict__ deg, float* __restrict__ invdeg, int n) {
    int i = blockIdx.x * blockDim.x + threadIdx.x;
    if (i < n) {
        int d = deg[i];
        invdeg[i] = 1.0f / (float)(d > 0 ? d : 1);
    }
}

__global__ void scanA_kernel(const int* __restrict__ deg, int* __restrict__ excl,
                             int* __restrict__ bsums, int n) {
    __shared__ int sh[SCANB];
    int tid = threadIdx.x;
    int i = blockIdx.x * SCANB + tid;
    int v = (i < n) ? deg[i] : 0;
    sh[tid] = v;
    __syncthreads();
    for (int off = 1; off < SCANB; off <<= 1) {
        int t = (tid >= off) ? sh[tid - off] : 0;
        __syncthreads();
        sh[tid] += t;
        __syncthreads();
    }
    if (i < n) excl[i] = sh[tid] - v;
    if (tid == SCANB - 1) bsums[blockIdx.x] = sh[tid];
}

__global__ void scanB_kernel(int* __restrict__ bsums, int nb) {
    __shared__ int sh[1024];
    int tid = threadIdx.x;
    int v = (tid < nb) ? bsums[tid] : 0;
    sh[tid] = v;
    __syncthreads();
    for (int off = 1; off < 1024; off <<= 1) {
        int t = (tid >= off) ? sh[tid - off] : 0;
        __syncthreads();
        sh[tid] += t;
        __syncthreads();
    }
    if (tid < nb) bsums[tid] = sh[tid] - v;
}

__global__ void scanC_kernel(int* __restrict__ rowptr, int* __restrict__ cursor,
                             const int* __restrict__ bsums, int n, int e) {
    int i = blockIdx.x * blockDim.x + threadIdx.x;
    if (i < n) {
        int r = rowptr[i] + bsums[i >> 10];
        rowptr[i] = r;
        cursor[i] = r;
    }
    if (i == 0) rowptr[n] = e;
}

__global__ void scatter_kernel(const int* __restrict__ src,
                               const int* __restrict__ dst,
                               int* __restrict__ cursor, int* __restrict__ col, int e) {
    int i = blockIdx.x * blockDim.x + threadIdx.x;
    if (i < e) {
        int d = dst[i];
        int s = src[i];
        int pos = atomicAdd(&cursor[d], 1);
        col[pos] = s;
    }
}

// ---------------- shared helpers -----------------------------------------------
// swizzled byte offset within a tile for (row, bf16 col k); rows are 512 B.
__device__ __forceinline__ uint32_t sw_off(int row, int k) {
    int chunk = k >> 3;                       // 16B chunk index 0..31
    int swc = chunk ^ (row & 7);
    return (uint32_t)(row * 512 + swc * 16 + (k & 7) * 2);
}

__device__ __forceinline__ unsigned long long pack2x2(__nv_bfloat162 p0, __nv_bfloat162 p1) {
    unsigned int u0 = *(unsigned int*)&p0;
    unsigned int u1 = *(unsigned int*)&p1;
    return (unsigned long long)u0 | ((unsigned long long)u1 << 32);
}

// split a float4 into hi/lo bf16 packed 8-byte values
__device__ __forceinline__ void split_f4(float4 v, unsigned long long& hi8,
                                         unsigned long long& lo8) {
    __nv_bfloat162 h01 = __floats2bfloat162_rn(v.x, v.y);
    __nv_bfloat162 h23 = __floats2bfloat162_rn(v.z, v.w);
    float r0 = v.x - __low2float(h01);
    float r1 = v.y - __high2float(h01);
    float r2 = v.z - __low2float(h23);
    float r3 = v.w - __high2float(h23);
    __nv_bfloat162 l01 = __floats2bfloat162_rn(r0, r1);
    __nv_bfloat162 l23 = __floats2bfloat162_rn(r2, r3);
    hi8 = pack2x2(h01, h23);
    lo8 = pack2x2(l01, l23);
}

__device__ __forceinline__ uint32_t smem_u32(const void* p) {
    uint32_t a;
    asm("{ .reg .u64 t; cvta.to.shared.u64 t, %1; cvt.u32.u64 %0, t; }" : "=r"(a) : "l"(p));
    return a;
}

#define LDSM_X4(d0, d1, d2, d3, addr) \
    asm volatile("ldmatrix.sync.aligned.m8n8.x4.shared.b16 {%0,%1,%2,%3}, [%4];" \
                 : "=r"(d0), "=r"(d1), "=r"(d2), "=r"(d3) : "r"(addr))

#define MMA_BF16(d, a, b) \
    asm volatile("mma.sync.aligned.m16n8k16.row.col.f32.bf16.bf16.f32 " \
                 "{%0,%1,%2,%3}, {%4,%5,%6,%7}, {%8,%9}, {%0,%1,%2,%3};" \
                 : "+f"((d)[0]), "+f"((d)[1]), "+f"((d)[2]), "+f"((d)[3]) \
                 : "r"((a)[0]), "r"((a)[1]), "r"((a)[2]), "r"((a)[3]), \
                   "r"((b)[0]), "r"((b)[1]))

// ---------------- W pre-convert: fp32 -> split-bf16, swizzled tile image -------
__global__ __launch_bounds__(256) void convert_w_kernel(
    const float* __restrict__ Wl, const float* __restrict__ Wr, char* __restrict__ img)
{
    int idx = blockIdx.x * blockDim.x + threadIdx.x;   // 0..8191
    if (idx >= 8192) return;
    int j = idx >> 5;
    int q = idx & 31;
    const float* srcw = (j < 128) ? (Wl + (size_t)j * D + q * 4)
                                  : (Wr + (size_t)(j - 128) * D + q * 4);
    float4 v = *(const float4*)srcw;
    unsigned long long hi8, lo8;
    split_f4(v, hi8, lo8);
    *(unsigned long long*)(img + sw_off(j, q * 4))       = hi8;
    *(unsigned long long*)(img + sw_off(j, 128 + q * 4)) = lo8;
}

// ---------------- tensor-core transform (persistent CTAs) ----------------------
#define TF_A_OFF   0
#define TF_B_OFF   65536
#define TF_SMEM_SZ 196608

__global__ __launch_bounds__(512) void transform_mma_kernel(
    const float* __restrict__ h,
    const char* __restrict__ wimg,
    const float* __restrict__ bias,
    float* __restrict__ z, float* __restrict__ yo, int n, int ntiles)
{
    extern __shared__ char smem[];
    const uint32_t sa = smem_u32(smem) + TF_A_OFF;
    const uint32_t sb = smem_u32(smem) + TF_B_OFF;
    int tid = threadIdx.x;

    // ---- load pre-converted W tile (131072 B straight copy) ----
    {
        const float4* wsrc = (const float4*)wimg;
        float4* bdst = (float4*)(smem + TF_B_OFF);
#pragma unroll
        for (int it = 0; it < 16; it++)
            bdst[tid + it * 512] = wsrc[tid + it * 512];
    }

    int wid = tid >> 5;
    int lane = tid & 31;
    int wm = wid >> 2;           // 0..3 -> row block of 32
    int wn = wid & 3;            // 0..3 -> col block of 64
    int R = wm * 32;
    int C = wn * 64;

    // ldmatrix lane address components
    int a_r = (lane & 7) + ((lane >> 3) & 1) * 8;
    int a_k = ((lane >> 4) & 1) * 8;
    int b_n = (lane & 7) + ((lane >> 4) & 1) * 8;
    int b_k = ((lane >> 3) & 1) * 8;
    int g  = lane >> 2;
    int tg = lane & 3;

    // hoist bias (warp-uniform: wn>=2 warps write y; wn<2 write z)
    bool is_y = (C >= 128);
    float bv0[8], bv1[8];
    if (is_y) {
#pragma unroll
        for (int nt = 0; nt < 8; nt++) {
            int yc = C - 128 + nt * 8 + tg * 2;
            bv0[nt] = __ldg(&bias[yc]);
            bv1[nt] = __ldg(&bias[yc + 1]);
        }
    }

    for (int tile = blockIdx.x; tile < ntiles; tile += gridDim.x) {
        int row0 = tile * 128;

        // ---- convert A: 128 rows x 128 fp32 -> hi|lo bf16 swizzled ----
        __syncthreads();   // prior iteration's ldmatrix reads must be done
#pragma unroll
        for (int it = 0; it < 8; it++) {
            int idx = tid + it * 512;
            int r = idx >> 5;
            int q = idx & 31;
            int grow = row0 + r;
            float4 v = make_float4(0.f, 0.f, 0.f, 0.f);
            if (grow < n) v = *(const float4*)(h + (size_t)grow * D + q * 4);
            unsigned long long hi8, lo8;
            split_f4(v, hi8, lo8);
            *(unsigned long long*)(smem + TF_A_OFF + sw_off(r, q * 4))       = hi8;
            *(unsigned long long*)(smem + TF_A_OFF + sw_off(r, 128 + q * 4)) = lo8;
        }
        __syncthreads();

        float acc[2][8][4];
#pragma unroll
        for (int mt = 0; mt < 2; mt++)
#pragma unroll
            for (int nt = 0; nt < 8; nt++)
#pragma unroll
                for (int i = 0; i < 4; i++) acc[mt][nt][i] = 0.f;

        // ---- fused 3-term loop: per k-chunk load Ahi, Alo, Bhi, Blo once ----
#pragma unroll
        for (int kc = 0; kc < 8; kc++) {
            int ka_hi = kc * 16 + a_k;
            int ka_lo = 128 + ka_hi;
            int kb_hi = kc * 16 + b_k;
            int kb_lo = 128 + kb_hi;

            uint32_t ahi[2][4], alo[2][4];
#pragma unroll
            for (int mt = 0; mt < 2; mt++) {
                uint32_t addr = sa + sw_off(R + mt * 16 + a_r, ka_hi);
                LDSM_X4(ahi[mt][0], ahi[mt][1], ahi[mt][2], ahi[mt][3], addr);
                addr = sa + sw_off(R + mt * 16 + a_r, ka_lo);
                LDSM_X4(alo[mt][0], alo[mt][1], alo[mt][2], alo[mt][3], addr);
            }
            // B-hi fragments: used by both hi@Whi and lo@Whi
            uint32_t bhi[8][2];
#pragma unroll
            for (int p = 0; p < 4; p++) {
                uint32_t addr = sb + sw_off(C + p * 16 + b_n, kb_hi);
                uint32_t d0, d1, d2, d3;
                LDSM_X4(d0, d1, d2, d3, addr);
                bhi[p * 2][0] = d0;     bhi[p * 2][1] = d1;
                bhi[p * 2 + 1][0] = d2; bhi[p * 2 + 1][1] = d3;
            }
#pragma unroll
            for (int mt = 0; mt < 2; mt++)
#pragma unroll
                for (int nt = 0; nt < 8; nt++) {
                    MMA_BF16(acc[mt][nt], ahi[mt], bhi[nt]);
                    MMA_BF16(acc[mt][nt], alo[mt], bhi[nt]);
                }
            // B-lo fragments: hi@Wlo
            uint32_t blo[8][2];
#pragma unroll
            for (int p = 0; p < 4; p++) {
                uint32_t addr = sb + sw_off(C + p * 16 + b_n, kb_lo);
                uint32_t d0, d1, d2, d3;
                LDSM_X4(d0, d1, d2, d3, addr);
                blo[p * 2][0] = d0;     blo[p * 2][1] = d1;
                blo[p * 2 + 1][0] = d2; blo[p * 2 + 1][1] = d3;
            }
#pragma unroll
            for (int mt = 0; mt < 2; mt++)
#pragma unroll
                for (int nt = 0; nt < 8; nt++)
                    MMA_BF16(acc[mt][nt], ahi[mt], blo[nt]);
        }

        // ---- epilogue (registers -> global; no SMEM) ----
#pragma unroll
        for (int mt = 0; mt < 2; mt++) {
            int r0g = row0 + R + mt * 16 + g;
            int r1g = r0g + 8;
            bool ok0 = (r0g < n), ok1 = (r1g < n);
            if (!is_y) {
#pragma unroll
                for (int nt = 0; nt < 8; nt++) {
                    int colg = C + nt * 8 + tg * 2;
                    if (ok0) *(float2*)(z + (size_t)r0g * D + colg) =
                        make_float2(acc[mt][nt][0], acc[mt][nt][1]);
                    if (ok1) *(float2*)(z + (size_t)r1g * D + colg) =
                        make_float2(acc[mt][nt][2], acc[mt][nt][3]);
                }
            } else {
#pragma unroll
                for (int nt = 0; nt < 8; nt++) {
                    int yc = C - 128 + nt * 8 + tg * 2;
                    if (ok0) *(float2*)(yo + (size_t)r0g * D + yc) =
                        make_float2(acc[mt][nt][0] + bv0[nt], acc[mt][nt][1] + bv1[nt]);
                    if (ok1) *(float2*)(yo + (size_t)r1g * D + yc) =
                        make_float2(acc[mt][nt][2] + bv0[nt], acc[mt][nt][3] + bv1[nt]);
                }
            }
        }
    }
}

// ---------------- aggregation: out[i] = act(sum z[col] * invdeg + y) -----------
__global__ __launch_bounds__(256) void aggregate_kernel(
    const float* __restrict__ z, const float* __restrict__ y,
    const int* __restrict__ rowptr, const int* __restrict__ col,
    const float* __restrict__ invdeg, float* __restrict__ out,
    int n, int do_relu)
{
    int warp = (int)((blockIdx.x * blockDim.x + threadIdx.x) >> 5);
    int lane = threadIdx.x & 31;
    if (warp >= n) return;

    int beg = rowptr[warp];
    int end = rowptr[warp + 1];

    float4 acc = make_float4(0.f, 0.f, 0.f, 0.f);
    for (int e = beg; e < end; e++) {
        int s = __ldg(&col[e]);
        float4 v = *(const float4*)(z + (size_t)s * D + lane * 4);
        acc.x += v.x; acc.y += v.y; acc.z += v.z; acc.w += v.w;
    }
    float inv = invdeg[warp];
    float4 yv = *(const float4*)(y + (size_t)warp * D + lane * 4);
    float4 o;
    o.x = fmaf(acc.x, inv, yv.x);
    o.y = fmaf(acc.y, inv, yv.y);
    o.z = fmaf(acc.z, inv, yv.z);
    o.w = fmaf(acc.w, inv, yv.w);
    if (do_relu) {
        o.x = fmaxf(o.x, 0.f); o.y = fmaxf(o.y, 0.f);
        o.z = fmaxf(o.z, 0.f); o.w = fmaxf(o.w, 0.f);
    }
    *(float4*)(out + (size_t)warp * D + lane * 4) = o;
}

// ---------------- launch -------------------------------------------------------
extern "C" void kernel_launch(void* const* d_in, const int* in_sizes, int n_in,
                              void* d_out, int out_size) {
    const float* x  = (const float*)d_in[0];
    const int*   ei = (const int*)d_in[1];      // int32 (JAX downcasts int64 w/o x64)
    const float* Wl[3] = {(const float*)d_in[2], (const float*)d_in[5], (const float*)d_in[8]};
    const float* Wr[3] = {(const float*)d_in[3], (const float*)d_in[6], (const float*)d_in[9]};
    const float* bb[3] = {(const float*)d_in[4], (const float*)d_in[7], (const float*)d_in[10]};
    float* out = (float*)d_out;

    int n = in_sizes[0] / D;        // 100000
    int e = in_sizes[1] / 2;        // 1600000
    const int* src = ei;
    const int* dst = ei + e;

    float *p_z, *p_y, *p_h1, *p_h2, *p_invdeg;
    int *p_col, *p_rowptr, *p_cursor, *p_deg, *p_bsums;
    char* p_wimg;
    cudaGetSymbolAddress((void**)&p_z,      g_z);
    cudaGetSymbolAddress((void**)&p_y,      g_y);
    cudaGetSymbolAddress((void**)&p_h1,     g_h1);
    cudaGetSymbolAddress((void**)&p_h2,     g_h2);
    cudaGetSymbolAddress((void**)&p_invdeg, g_invdeg);
    cudaGetSymbolAddress((void**)&p_col,    g_col);
    cudaGetSymbolAddress((void**)&p_rowptr, g_rowptr);
    cudaGetSymbolAddress((void**)&p_cursor, g_cursor);
    cudaGetSymbolAddress((void**)&p_deg,    g_deg);
    cudaGetSymbolAddress((void**)&p_bsums,  g_bsums);
    cudaGetSymbolAddress((void**)&p_wimg,   g_wimg);

    static int smem_set = 0;
    if (!smem_set) {
        cudaFuncSetAttribute(transform_mma_kernel,
                             cudaFuncAttributeMaxDynamicSharedMemorySize, TF_SMEM_SZ);
        smem_set = 1;
    }

    int nb_n = (n + 255) / 256;
    int nb_e = (e + 255) / 256;
    int nb_scan = (n + SCANB - 1) / SCANB;
    int ntiles = (n + 127) / 128;
    int nb_ag = (n * 32 + 255) / 256;
    float* houts[3] = {p_h1, p_h2, out};

    // Launch order arranged so transform_mma_kernel is launch index 5
    // (ncu capture is -s 5 -c 1): cw,cw,cw,zero,hist,transform1,...
    for (int l = 0; l < 3; l++)                                        // 0,1,2
        convert_w_kernel<<<32, 256>>>(Wl[l], Wr[l], p_wimg + (size_t)l * 131072);
    zero_deg_kernel<<<nb_n, 256>>>(p_deg, n);                          // 3
    hist_kernel<<<nb_e, 256>>>(dst, p_deg, e);                         // 4
    transform_mma_kernel<<<148, 512, TF_SMEM_SZ>>>(x, p_wimg, bb[0],   // 5 (profiled)
                                                   p_z, p_y, n, ntiles);
    invdeg_kernel<<<nb_n, 256>>>(p_deg, p_invdeg, n);                  // 6
    scanA_kernel<<<nb_scan, SCANB>>>(p_deg, p_rowptr, p_bsums, n);     // 7
    scanB_kernel<<<1, 1024>>>(p_bsums, nb_scan);                       // 8
    scanC_kernel<<<nb_n, 256>>>(p_rowptr, p_cursor, p_bsums, n, e);    // 9
    scatter_kernel<<<nb_e, 256>>>(src, dst, p_cursor, p_col, e);       // 10
    aggregate_kernel<<<nb_ag, 256>>>(p_z, p_y, p_rowptr, p_col, p_invdeg,
                                     houts[0], n, 1);                  // 11
    for (int l = 1; l < 3; l++) {
        transform_mma_kernel<<<148, 512, TF_SMEM_SZ>>>(houts[l - 1],
                                                       p_wimg + (size_t)l * 131072,
                                                       bb[l], p_z, p_y, n, ntiles);
        aggregate_kernel<<<nb_ag, 256>>>(p_z, p_y, p_rowptr, p_col, p_invdeg,
                                         houts[l], n, (l < 2) ? 1 : 0);
    }
}

// round 8
// speedup vs baseline: 2.2988x; 1.0949x over previous
#include <cuda_runtime.h>
#include <cuda_bf16.h>
#include <cuda_fp16.h>
#include <stdint.h>

// Problem constants (fixed by the dataset)
#define NMAX   100000
#define EMAX   1600000
#define D      128
#define SCANB  1024

// ---------------- device scratch (allocation-free rule: __device__ globals) ----
__device__ __half g_zh[NMAX * D];     // fp16 message term (gathered by aggregate)
__device__ float g_y[NMAX * D];
__device__ float g_h1[NMAX * D];
__device__ float g_h2[NMAX * D];
__device__ int   g_col[EMAX];
__device__ int   g_rowptr[NMAX + 1];
__device__ int   g_cursor[NMAX];
__device__ int   g_deg[NMAX];
__device__ float g_invdeg[NMAX];
__device__ int   g_bsums[1024];
// pre-converted, pre-swizzled W tile images (split-bf16), one per layer
__device__ __align__(16) char g_wimg[3][131072];

// ---------------- CSR build ---------------------------------------------------
__global__ void zero_deg_kernel(int* deg, int n) {
    int i = blockIdx.x * blockDim.x + threadIdx.x;
    if (i < n) deg[i] = 0;
}

__global__ void hist_kernel(const int* __restrict__ dst, int* __restrict__ deg, int e) {
    int i = blockIdx.x * blockDim.x + threadIdx.x;
    if (i < e) atomicAdd(&deg[dst[i]], 1);
}

__global__ void invdeg_kernel(const int* __restrict__ deg, float* __restrict__ invdeg, int n) {
    int i = blockIdx.x * blockDim.x + threadIdx.x;
    if (i < n) {
        int d = deg[i];
        invdeg[i] = 1.0f / (float)(d > 0 ? d : 1);
    }
}

__global__ void scanA_kernel(const int* __restrict__ deg, int* __restrict__ excl,
                             int* __restrict__ bsums, int n) {
    __shared__ int sh[SCANB];
    int tid = threadIdx.x;
    int i = blockIdx.x * SCANB + tid;
    int v = (i < n) ? deg[i] : 0;
    sh[tid] = v;
    __syncthreads();
    for (int off = 1; off < SCANB; off <<= 1) {
        int t = (tid >= off) ? sh[tid - off] : 0;
        __syncthreads();
        sh[tid] += t;
        __syncthreads();
    }
    if (i < n) excl[i] = sh[tid] - v;
    if (tid == SCANB - 1) bsums[blockIdx.x] = sh[tid];
}

__global__ void scanB_kernel(int* __restrict__ bsums, int nb) {
    __shared__ int sh[1024];
    int tid = threadIdx.x;
    int v = (tid < nb) ? bsums[tid] : 0;
    sh[tid] = v;
    __syncthreads();
    for (int off = 1; off < 1024; off <<= 1) {
        int t = (tid >= off) ? sh[tid - off] : 0;
        __syncthreads();
        sh[tid] += t;
        __syncthreads();
    }
    if (tid < nb) bsums[tid] = sh[tid] - v;
}

__global__ void scanC_kernel(int* __restrict__ rowptr, int* __restrict__ cursor,
                             const int* __restrict__ bsums, int n, int e) {
    int i = blockIdx.x * blockDim.x + threadIdx.x;
    if (i < n) {
        int r = rowptr[i] + bsums[i >> 10];
        rowptr[i] = r;
        cursor[i] = r;
    }
    if (i == 0) rowptr[n] = e;
}

__global__ void scatter_kernel(const int* __restrict__ src,
                               const int* __restrict__ dst,
                               int* __restrict__ cursor, int* __restrict__ col, int e) {
    int i = blockIdx.x * blockDim.x + threadIdx.x;
    if (i < e) {
        int d = dst[i];
        int s = src[i];
        int pos = atomicAdd(&cursor[d], 1);
        col[pos] = s;
    }
}

// ---------------- shared helpers -----------------------------------------------
// swizzled byte offset within a tile for (row, bf16 col k); rows are 512 B.
__device__ __forceinline__ uint32_t sw_off(int row, int k) {
    int chunk = k >> 3;                       // 16B chunk index 0..31
    int swc = chunk ^ (row & 7);
    return (uint32_t)(row * 512 + swc * 16 + (k & 7) * 2);
}

__device__ __forceinline__ unsigned long long pack2x2(__nv_bfloat162 p0, __nv_bfloat162 p1) {
    unsigned int u0 = *(unsigned int*)&p0;
    unsigned int u1 = *(unsigned int*)&p1;
    return (unsigned long long)u0 | ((unsigned long long)u1 << 32);
}

// split a float4 into hi/lo bf16 packed 8-byte values
__device__ __forceinline__ void split_f4(float4 v, unsigned long long& hi8,
                                         unsigned long long& lo8) {
    __nv_bfloat162 h01 = __floats2bfloat162_rn(v.x, v.y);
    __nv_bfloat162 h23 = __floats2bfloat162_rn(v.z, v.w);
    float r0 = v.x - __low2float(h01);
    float r1 = v.y - __high2float(h01);
    float r2 = v.z - __low2float(h23);
    float r3 = v.w - __high2float(h23);
    __nv_bfloat162 l01 = __floats2bfloat162_rn(r0, r1);
    __nv_bfloat162 l23 = __floats2bfloat162_rn(r2, r3);
    hi8 = pack2x2(h01, h23);
    lo8 = pack2x2(l01, l23);
}

__device__ __forceinline__ uint32_t smem_u32(const void* p) {
    uint32_t a;
    asm("{ .reg .u64 t; cvta.to.shared.u64 t, %1; cvt.u32.u64 %0, t; }" : "=r"(a) : "l"(p));
    return a;
}

#define LDSM_X4(d0, d1, d2, d3, addr) \
    asm volatile("ldmatrix.sync.aligned.m8n8.x4.shared.b16 {%0,%1,%2,%3}, [%4];" \
                 : "=r"(d0), "=r"(d1), "=r"(d2), "=r"(d3) : "r"(addr))

#define MMA_BF16(d, a, b) \
    asm volatile("mma.sync.aligned.m16n8k16.row.col.f32.bf16.bf16.f32 " \
                 "{%0,%1,%2,%3}, {%4,%5,%6,%7}, {%8,%9}, {%0,%1,%2,%3};" \
                 : "+f"((d)[0]), "+f"((d)[1]), "+f"((d)[2]), "+f"((d)[3]) \
                 : "r"((a)[0]), "r"((a)[1]), "r"((a)[2]), "r"((a)[3]), \
                   "r"((b)[0]), "r"((b)[1]))

// ---------------- W pre-convert: fp32 -> split-bf16, swizzled tile image -------
__global__ __launch_bounds__(256) void convert_w_kernel(
    const float* __restrict__ Wl, const float* __restrict__ Wr, char* __restrict__ img)
{
    int idx = blockIdx.x * blockDim.x + threadIdx.x;   // 0..8191
    if (idx >= 8192) return;
    int j = idx >> 5;
    int q = idx & 31;
    const float* srcw = (j < 128) ? (Wl + (size_t)j * D + q * 4)
                                  : (Wr + (size_t)(j - 128) * D + q * 4);
    float4 v = *(const float4*)srcw;
    unsigned long long hi8, lo8;
    split_f4(v, hi8, lo8);
    *(unsigned long long*)(img + sw_off(j, q * 4))       = hi8;
    *(unsigned long long*)(img + sw_off(j, 128 + q * 4)) = lo8;
}

// ---------------- tensor-core transform (persistent CTAs) ----------------------
#define TF_A_OFF   0
#define TF_B_OFF   65536
#define TF_SMEM_SZ 196608

__global__ __launch_bounds__(512) void transform_mma_kernel(
    const float* __restrict__ h,
    const char* __restrict__ wimg,
    const float* __restrict__ bias,
    __half* __restrict__ zh, float* __restrict__ yo, int n, int ntiles)
{
    extern __shared__ char smem[];
    const uint32_t sa = smem_u32(smem) + TF_A_OFF;
    const uint32_t sb = smem_u32(smem) + TF_B_OFF;
    int tid = threadIdx.x;

    // ---- load pre-converted W tile (131072 B straight copy) ----
    {
        const float4* wsrc = (const float4*)wimg;
        float4* bdst = (float4*)(smem + TF_B_OFF);
#pragma unroll
        for (int it = 0; it < 16; it++)
            bdst[tid + it * 512] = wsrc[tid + it * 512];
    }

    int wid = tid >> 5;
    int lane = tid & 31;
    int wm = wid >> 2;           // 0..3 -> row block of 32
    int wn = wid & 3;            // 0..3 -> col block of 64
    int R = wm * 32;
    int C = wn * 64;

    // ldmatrix lane address components
    int a_r = (lane & 7) + ((lane >> 3) & 1) * 8;
    int a_k = ((lane >> 4) & 1) * 8;
    int b_n = (lane & 7) + ((lane >> 4) & 1) * 8;
    int b_k = ((lane >> 3) & 1) * 8;
    int g  = lane >> 2;
    int tg = lane & 3;

    // hoist bias (warp-uniform: wn>=2 warps write y; wn<2 write z)
    bool is_y = (C >= 128);
    float bv0[8], bv1[8];
    if (is_y) {
#pragma unroll
        for (int nt = 0; nt < 8; nt++) {
            int yc = C - 128 + nt * 8 + tg * 2;
            bv0[nt] = __ldg(&bias[yc]);
            bv1[nt] = __ldg(&bias[yc + 1]);
        }
    }

    for (int tile = blockIdx.x; tile < ntiles; tile += gridDim.x) {
        int row0 = tile * 128;

        // ---- convert A: 128 rows x 128 fp32 -> hi|lo bf16 swizzled ----
        __syncthreads();   // prior iteration's ldmatrix reads must be done
#pragma unroll
        for (int it = 0; it < 8; it++) {
            int idx = tid + it * 512;
            int r = idx >> 5;
            int q = idx & 31;
            int grow = row0 + r;
            float4 v = make_float4(0.f, 0.f, 0.f, 0.f);
            if (grow < n) v = *(const float4*)(h + (size_t)grow * D + q * 4);
            unsigned long long hi8, lo8;
            split_f4(v, hi8, lo8);
            *(unsigned long long*)(smem + TF_A_OFF + sw_off(r, q * 4))       = hi8;
            *(unsigned long long*)(smem + TF_A_OFF + sw_off(r, 128 + q * 4)) = lo8;
        }
        __syncthreads();

        float acc[2][8][4];
#pragma unroll
        for (int mt = 0; mt < 2; mt++)
#pragma unroll
            for (int nt = 0; nt < 8; nt++)
#pragma unroll
                for (int i = 0; i < 4; i++) acc[mt][nt][i] = 0.f;

        // ---- fused 3-term loop: per k-chunk load Ahi, Alo, Bhi, Blo once ----
#pragma unroll
        for (int kc = 0; kc < 8; kc++) {
            int ka_hi = kc * 16 + a_k;
            int ka_lo = 128 + ka_hi;
            int kb_hi = kc * 16 + b_k;
            int kb_lo = 128 + kb_hi;

            uint32_t ahi[2][4], alo[2][4];
#pragma unroll
            for (int mt = 0; mt < 2; mt++) {
                uint32_t addr = sa + sw_off(R + mt * 16 + a_r, ka_hi);
                LDSM_X4(ahi[mt][0], ahi[mt][1], ahi[mt][2], ahi[mt][3], addr);
                addr = sa + sw_off(R + mt * 16 + a_r, ka_lo);
                LDSM_X4(alo[mt][0], alo[mt][1], alo[mt][2], alo[mt][3], addr);
            }
            // B-hi fragments: used by both hi@Whi and lo@Whi
            uint32_t bhi[8][2];
#pragma unroll
            for (int p = 0; p < 4; p++) {
                uint32_t addr = sb + sw_off(C + p * 16 + b_n, kb_hi);
                uint32_t d0, d1, d2, d3;
                LDSM_X4(d0, d1, d2, d3, addr);
                bhi[p * 2][0] = d0;     bhi[p * 2][1] = d1;
                bhi[p * 2 + 1][0] = d2; bhi[p * 2 + 1][1] = d3;
            }
#pragma unroll
            for (int mt = 0; mt < 2; mt++)
#pragma unroll
                for (int nt = 0; nt < 8; nt++) {
                    MMA_BF16(acc[mt][nt], ahi[mt], bhi[nt]);
                    MMA_BF16(acc[mt][nt], alo[mt], bhi[nt]);
                }
            // B-lo fragments: hi@Wlo
            uint32_t blo[8][2];
#pragma unroll
            for (int p = 0; p < 4; p++) {
                uint32_t addr = sb + sw_off(C + p * 16 + b_n, kb_lo);
                uint32_t d0, d1, d2, d3;
                LDSM_X4(d0, d1, d2, d3, addr);
                blo[p * 2][0] = d0;     blo[p * 2][1] = d1;
                blo[p * 2 + 1][0] = d2; blo[p * 2 + 1][1] = d3;
            }
#pragma unroll
            for (int mt = 0; mt < 2; mt++)
#pragma unroll
                for (int nt = 0; nt < 8; nt++)
                    MMA_BF16(acc[mt][nt], ahi[mt], blo[nt]);
        }

        // ---- epilogue (registers -> global; no SMEM) ----
#pragma unroll
        for (int mt = 0; mt < 2; mt++) {
            int r0g = row0 + R + mt * 16 + g;
            int r1g = r0g + 8;
            bool ok0 = (r0g < n), ok1 = (r1g < n);
            if (!is_y) {
                // z path: convert to fp16, store half2 (4 B)
#pragma unroll
                for (int nt = 0; nt < 8; nt++) {
                    int colg = C + nt * 8 + tg * 2;
                    if (ok0) *(__half2*)(zh + (size_t)r0g * D + colg) =
                        __floats2half2_rn(acc[mt][nt][0], acc[mt][nt][1]);
                    if (ok1) *(__half2*)(zh + (size_t)r1g * D + colg) =
                        __floats2half2_rn(acc[mt][nt][2], acc[mt][nt][3]);
                }
            } else {
#pragma unroll
                for (int nt = 0; nt < 8; nt++) {
                    int yc = C - 128 + nt * 8 + tg * 2;
                    if (ok0) *(float2*)(yo + (size_t)r0g * D + yc) =
                        make_float2(acc[mt][nt][0] + bv0[nt], acc[mt][nt][1] + bv1[nt]);
                    if (ok1) *(float2*)(yo + (size_t)r1g * D + yc) =
                        make_float2(acc[mt][nt][2] + bv0[nt], acc[mt][nt][3] + bv1[nt]);
                }
            }
        }
    }
}

// ---------------- aggregation: out[i] = act(sum zh[col] * invdeg + y) ----------
// One warp per node; each lane owns 4 cols = 8 B of fp16 z per gathered row.
__global__ __launch_bounds__(256) void aggregate_kernel(
    const __half* __restrict__ zh, const float* __restrict__ y,
    const int* __restrict__ rowptr, const int* __restrict__ col,
    const float* __restrict__ invdeg, float* __restrict__ out,
    int n, int do_relu)
{
    int warp = (int)((blockIdx.x * blockDim.x + threadIdx.x) >> 5);
    int lane = threadIdx.x & 31;
    if (warp >= n) return;

    int beg = rowptr[warp];
    int end = rowptr[warp + 1];

    float4 acc = make_float4(0.f, 0.f, 0.f, 0.f);
    for (int e = beg; e < end; e++) {
        int s = __ldg(&col[e]);
        uint2 raw = *(const uint2*)(zh + (size_t)s * D + lane * 4);
        __half2 p0 = *(__half2*)&raw.x;
        __half2 p1 = *(__half2*)&raw.y;
        float2 f0 = __half22float2(p0);
        float2 f1 = __half22float2(p1);
        acc.x += f0.x; acc.y += f0.y; acc.z += f1.x; acc.w += f1.y;
    }
    float inv = invdeg[warp];
    float4 yv = *(const float4*)(y + (size_t)warp * D + lane * 4);
    float4 o;
    o.x = fmaf(acc.x, inv, yv.x);
    o.y = fmaf(acc.y, inv, yv.y);
    o.z = fmaf(acc.z, inv, yv.z);
    o.w = fmaf(acc.w, inv, yv.w);
    if (do_relu) {
        o.x = fmaxf(o.x, 0.f); o.y = fmaxf(o.y, 0.f);
        o.z = fmaxf(o.z, 0.f); o.w = fmaxf(o.w, 0.f);
    }
    *(float4*)(out + (size_t)warp * D + lane * 4) = o;
}

// ---------------- launch -------------------------------------------------------
extern "C" void kernel_launch(void* const* d_in, const int* in_sizes, int n_in,
                              void* d_out, int out_size) {
    const float* x  = (const float*)d_in[0];
    const int*   ei = (const int*)d_in[1];      // int32 (JAX downcasts int64 w/o x64)
    const float* Wl[3] = {(const float*)d_in[2], (const float*)d_in[5], (const float*)d_in[8]};
    const float* Wr[3] = {(const float*)d_in[3], (const float*)d_in[6], (const float*)d_in[9]};
    const float* bb[3] = {(const float*)d_in[4], (const float*)d_in[7], (const float*)d_in[10]};
    float* out = (float*)d_out;

    int n = in_sizes[0] / D;        // 100000
    int e = in_sizes[1] / 2;        // 1600000
    const int* src = ei;
    const int* dst = ei + e;

    float *p_y, *p_h1, *p_h2, *p_invdeg;
    __half* p_zh;
    int *p_col, *p_rowptr, *p_cursor, *p_deg, *p_bsums;
    char* p_wimg;
    cudaGetSymbolAddress((void**)&p_zh,     g_zh);
    cudaGetSymbolAddress((void**)&p_y,      g_y);
    cudaGetSymbolAddress((void**)&p_h1,     g_h1);
    cudaGetSymbolAddress((void**)&p_h2,     g_h2);
    cudaGetSymbolAddress((void**)&p_invdeg, g_invdeg);
    cudaGetSymbolAddress((void**)&p_col,    g_col);
    cudaGetSymbolAddress((void**)&p_rowptr, g_rowptr);
    cudaGetSymbolAddress((void**)&p_cursor, g_cursor);
    cudaGetSymbolAddress((void**)&p_deg,    g_deg);
    cudaGetSymbolAddress((void**)&p_bsums,  g_bsums);
    cudaGetSymbolAddress((void**)&p_wimg,   g_wimg);

    static int smem_set = 0;
    if (!smem_set) {
        cudaFuncSetAttribute(transform_mma_kernel,
                             cudaFuncAttributeMaxDynamicSharedMemorySize, TF_SMEM_SZ);
        smem_set = 1;
    }

    int nb_n = (n + 255) / 256;
    int nb_e = (e + 255) / 256;
    int nb_scan = (n + SCANB - 1) / SCANB;
    int ntiles = (n + 127) / 128;
    int nb_ag = (n * 32 + 255) / 256;
    float* houts[3] = {p_h1, p_h2, out};

    // CSR build interleaved with W convert + first transform (independent work)
    for (int l = 0; l < 3; l++)
        convert_w_kernel<<<32, 256>>>(Wl[l], Wr[l], p_wimg + (size_t)l * 131072);
    zero_deg_kernel<<<nb_n, 256>>>(p_deg, n);
    hist_kernel<<<nb_e, 256>>>(dst, p_deg, e);
    transform_mma_kernel<<<148, 512, TF_SMEM_SZ>>>(x, p_wimg, bb[0],
                                                   p_zh, p_y, n, ntiles);
    invdeg_kernel<<<nb_n, 256>>>(p_deg, p_invdeg, n);
    scanA_kernel<<<nb_scan, SCANB>>>(p_deg, p_rowptr, p_bsums, n);
    scanB_kernel<<<1, 1024>>>(p_bsums, nb_scan);
    scanC_kernel<<<nb_n, 256>>>(p_rowptr, p_cursor, p_bsums, n, e);
    scatter_kernel<<<nb_e, 256>>>(src, dst, p_cursor, p_col, e);
    aggregate_kernel<<<nb_ag, 256>>>(p_zh, p_y, p_rowptr, p_col, p_invdeg,
                                     houts[0], n, 1);
    for (int l = 1; l < 3; l++) {
        transform_mma_kernel<<<148, 512, TF_SMEM_SZ>>>(houts[l - 1],
                                                       p_wimg + (size_t)l * 131072,
                                                       bb[l], p_zh, p_y, n, ntiles);
        aggregate_kernel<<<nb_ag, 256>>>(p_zh, p_y, p_rowptr, p_col, p_invdeg,
                                         houts[l], n, (l < 2) ? 1 : 0);
    }
}